// round 6
// baseline (speedup 1.0000x reference)
#include <cuda_runtime.h>
#include <cstdint>

// Output: (256, 64, 48, 320) float32
// out[n][c][i][j] = x[box_img[n]][c][ y0+i*h/48 ][ x0+j*w/320 ]

#define H_IN   200
#define W_IN   320
#define C_IN   64
#define N_BOX  256
#define H_OUT  48
#define W_OUT  320

#define C_PASS 4                  // channels per block
#define NCG    (C_IN / C_PASS)    // 16 channel-groups
#define J4     (W_OUT / 4)        // 80
#define NTHREADS (J4 * C_PASS)    // 320

__global__ __launch_bounds__(NTHREADS, 5)
void roi_crop_kernel(const float* __restrict__ x,
                     const int*  __restrict__ bboxes,
                     const int*  __restrict__ box_img,
                     float*      __restrict__ out)
{
    // One block per (n, channel-group). Each thread owns ONE channel and one
    // float4 column slot, and walks all 48 output rows -> each block emits
    // four contiguous 61 KB write streams (max DRAM page locality).
    const int bi = blockIdx.x;
    const int cg = bi % NCG;
    const int n  = bi / NCG;

    const int tid  = threadIdx.x;
    const int j4   = tid % J4;                // float4 slot along W_OUT
    const int c    = cg * C_PASS + tid / J4;  // this thread's channel

    // bbox math — once per thread
    int4 b = __ldg(reinterpret_cast<const int4*>(bboxes) + n);
    int x0 = min(max(b.x, 0), W_IN - 1);
    int y0 = min(max(b.y, 0), H_IN - 1);
    int x1 = min(max(b.z, 0), W_IN - 1);
    int y1 = min(max(b.w, 0), H_IN - 1);
    x1 = max(x1, x0);
    y1 = max(y1, y0);
    const int h = y1 - y0 + 1;
    const int w = x1 - x0 + 1;

    const int img = __ldg(box_img + n);

    const int j  = j4 * 4;
    const int c0 = x0 + ((j + 0) * w) / W_OUT;
    const int c1 = x0 + ((j + 1) * w) / W_OUT;
    const int c2 = x0 + ((j + 2) * w) / W_OUT;
    const int c3 = x0 + ((j + 3) * w) / W_OUT;

    // Channel base of source image plane
    const float* plane = x + ((size_t)img * C_IN + c) * (size_t)(H_IN * W_IN);
    // Output: walk i with stride one row (1280 B) -> contiguous per channel
    float* dst = out + (((size_t)n * C_IN + c) * H_OUT) * (size_t)W_OUT + j;

    #pragma unroll 4
    for (int i = 0; i < H_OUT; ++i) {
        const int r = y0 + (i * h) / H_OUT;          // monotone in i
        const float* src = plane + (size_t)r * W_IN;

        float4 v;
        v.x = __ldg(src + c0);
        v.y = __ldg(src + c1);
        v.z = __ldg(src + c2);
        v.w = __ldg(src + c3);

        __stcs(reinterpret_cast<float4*>(dst), v);   // evict-first store
        dst += W_OUT;
    }
}

extern "C" void kernel_launch(void* const* d_in, const int* in_sizes, int n_in,
                              void* d_out, int out_size)
{
    const float* x       = (const float*)d_in[0];
    const int*   bboxes  = (const int*)  d_in[1];
    const int*   box_img = (const int*)  d_in[2];
    float*       out     = (float*)      d_out;

    const int blocks = N_BOX * NCG;   // 4096
    roi_crop_kernel<<<blocks, NTHREADS>>>(x, bboxes, box_img, out);
}

// round 9
// speedup vs baseline: 1.0543x; 1.0543x over previous
#include <cuda_runtime.h>
#include <cstdint>

// Output: (256, 64, 48, 320) float32
// out[n][c][i][j] = x[box_img[n]][c][ y0+i*h/48 ][ x0+j*w/320 ]

#define H_IN   200
#define W_IN   320
#define C_IN   64
#define N_BOX  256
#define H_OUT  48
#define W_OUT  320

#define C_PASS 4                  // channels per pass
#define NPASS  (C_IN / C_PASS)    // 16
#define J4     (W_OUT / 4)        // 80
#define NTHREADS (J4 * C_PASS)    // 320

__global__ __launch_bounds__(NTHREADS, 6)
void roi_crop_kernel(const float* __restrict__ x,
                     const int*  __restrict__ bboxes,
                     const int*  __restrict__ box_img,
                     float*      __restrict__ out)
{
    // One block per (n, i). blockIdx.x = n * H_OUT + i
    const int bi = blockIdx.x;
    const int i  = bi % H_OUT;
    const int n  = bi / H_OUT;

    const int tid  = threadIdx.x;
    const int j4   = tid % J4;      // which float4 along W_OUT
    const int csub = tid / J4;      // 0..3, channel sub-slot

    // bbox math — once per thread, hoisted out of the channel loop
    int4 b = __ldg(reinterpret_cast<const int4*>(bboxes) + n);
    int x0 = min(max(b.x, 0), W_IN - 1);
    int y0 = min(max(b.y, 0), H_IN - 1);
    int x1 = min(max(b.z, 0), W_IN - 1);
    int y1 = min(max(b.w, 0), H_IN - 1);
    x1 = max(x1, x0);
    y1 = max(y1, y0);
    const int h = y1 - y0 + 1;
    const int w = x1 - x0 + 1;

    const int r   = y0 + (i * h) / H_OUT;
    const int img = __ldg(box_img + n);

    const int j  = j4 * 4;
    const int c0 = x0 + ((j + 0) * w) / W_OUT;
    const int c1 = x0 + ((j + 1) * w) / W_OUT;
    const int c2 = x0 + ((j + 2) * w) / W_OUT;
    const int c3 = x0 + ((j + 3) * w) / W_OUT;

    const float* src = x
        + ((size_t)img * C_IN + csub) * (size_t)(H_IN * W_IN)
        + (size_t)r * W_IN;
    float* dst = out
        + (((size_t)n * C_IN + csub) * H_OUT + i) * (size_t)W_OUT + j;

    const size_t src_stride = (size_t)C_PASS * H_IN * W_IN;   // floats
    const size_t dst_stride = (size_t)C_PASS * H_OUT * W_OUT; // floats

    // Depth-2 software pipeline: two gather sets in flight ahead of each store.
    float4 v0, v1;
    v0.x = __ldg(src + c0);  v0.y = __ldg(src + c1);
    v0.z = __ldg(src + c2);  v0.w = __ldg(src + c3);
    src += src_stride;
    v1.x = __ldg(src + c0);  v1.y = __ldg(src + c1);
    v1.z = __ldg(src + c2);  v1.w = __ldg(src + c3);

    #pragma unroll
    for (int p = 0; p < NPASS - 2; ++p) {
        const float* nsrc = src + src_stride;
        float4 nv;
        nv.x = __ldg(nsrc + c0);  nv.y = __ldg(nsrc + c1);
        nv.z = __ldg(nsrc + c2);  nv.w = __ldg(nsrc + c3);

        __stcs(reinterpret_cast<float4*>(dst), v0);  // evict-first store

        v0 = v1;
        v1 = nv;
        src = nsrc;
        dst += dst_stride;
    }
    __stcs(reinterpret_cast<float4*>(dst), v0);
    dst += dst_stride;
    __stcs(reinterpret_cast<float4*>(dst), v1);
}

extern "C" void kernel_launch(void* const* d_in, const int* in_sizes, int n_in,
                              void* d_out, int out_size)
{
    const float* x       = (const float*)d_in[0];
    const int*   bboxes  = (const int*)  d_in[1];
    const int*   box_img = (const int*)  d_in[2];
    float*       out     = (float*)      d_out;

    const int blocks = N_BOX * H_OUT;   // 12288
    roi_crop_kernel<<<blocks, NTHREADS>>>(x, bboxes, box_img, out);
}